// round 15
// baseline (speedup 1.0000x reference)
#include <cuda_runtime.h>
#include <cuda_fp16.h>
#include <cstdint>
#include <cstddef>

#define BATCH   16384
#define DIN     2048
#define DHALF   1024
#define H1DIM   512
#define H2DIM   128
#define NEXP    8
#define NCLS    10
#define NV      9

// ---------------------------------------------------------------------------
// Scratch (__device__ globals) — R11 layouts
// ---------------------------------------------------------------------------
__device__ uint4 g_At [(size_t)128 * 128 * 8 * 32];
__device__ uint4 g_W1t[(size_t)36 * 128 * 8 * 32];
__device__ uint4 g_W2t[(size_t)9 * 32 * 8 * 32];
__device__ uint4 g_H1t[(size_t)9 * 128 * 32 * 8 * 32];
__device__ float g_H2 [(size_t)NV * BATCH * H2DIM];

// ---------------------------------------------------------------------------
// helpers
// ---------------------------------------------------------------------------
__device__ __forceinline__ uint32_t smem_u32(const void* p) {
    uint32_t a;
    asm("{ .reg .u64 t; cvta.to.shared.u64 t, %1; cvt.u32.u64 %0, t; }" : "=r"(a) : "l"(p));
    return a;
}

__device__ __forceinline__ uint32_t pack_h2(float x, float y) {
    __half2 h = __floats2half2_rn(x, y);
    return *(uint32_t*)&h;
}

#define CP16(ds, gs) \
    asm volatile("cp.async.cg.shared.global [%0], [%1], 16;" :: "r"(ds), "l"(gs))
#define CP_COMMIT()  asm volatile("cp.async.commit_group;" ::: "memory")
#define CP_WAIT2()   asm volatile("cp.async.wait_group 2;" ::: "memory")
#define CP_WAIT1()   asm volatile("cp.async.wait_group 1;" ::: "memory")
#define CP_WAIT0()   asm volatile("cp.async.wait_group 0;" ::: "memory")

// m16n8k16 fp16 MMA, fp32 accum, D += A*B (row.col)
__device__ __forceinline__ void mma16(float* d, const uint32_t* a, const uint32_t* b) {
    asm volatile(
        "mma.sync.aligned.m16n8k16.row.col.f32.f16.f16.f32 "
        "{%0,%1,%2,%3}, {%4,%5,%6,%7}, {%8,%9}, {%0,%1,%2,%3};"
        : "+f"(d[0]), "+f"(d[1]), "+f"(d[2]), "+f"(d[3])
        : "r"(a[0]), "r"(a[1]), "r"(a[2]), "r"(a[3]), "r"(b[0]), "r"(b[1]));
}

// ---------------------------------------------------------------------------
// Merged prep (R11 exact)
// ---------------------------------------------------------------------------
#define PA_BLOCKS   4096
#define PW1_BLOCKS  4608
#define PW2_BLOCKS  288
#define PREP_BLOCKS (PA_BLOCKS + PW1_BLOCKS + PW2_BLOCKS)

__device__ __forceinline__ void prep_W_body(
    const float* __restrict__ gw, const float* __restrict__ ew,
    uint4* dst, int K, int N, int kt, int nb, int v, int tid)
{
    const float* W = (v == 0) ? gw : (ew + (size_t)(v - 1) * K * N);
    const int KT = K / 16, NB = N / 128;
    const int k0 = kt * 16;

    if (tid < 256) {
        const int ntp = tid >> 5, l = tid & 31;
        const int c2 = 2 * (l & 3), g = l >> 2;
        const int n0 = nb * 128 + ntp * 16 + g;
        const int n1 = n0 + 8;
        uint4 o;
        o.x = pack_h2(W[(size_t)(k0 + c2)     * N + n0], W[(size_t)(k0 + c2 + 1) * N + n0]);
        o.y = pack_h2(W[(size_t)(k0 + c2 + 8) * N + n0], W[(size_t)(k0 + c2 + 9) * N + n0]);
        o.z = pack_h2(W[(size_t)(k0 + c2)     * N + n1], W[(size_t)(k0 + c2 + 1) * N + n1]);
        o.w = pack_h2(W[(size_t)(k0 + c2 + 8) * N + n1], W[(size_t)(k0 + c2 + 9) * N + n1]);
        dst[((((size_t)v * NB + nb) * KT + kt) * 8 + ntp) * 32 + l] = o;
    }
}

__global__ __launch_bounds__(256) void prep_all(
    const float* __restrict__ fs, const float* __restrict__ fp,
    const float* __restrict__ gW1, const float* __restrict__ eW1,
    const float* __restrict__ gW2, const float* __restrict__ eW2)
{
    const int bid = blockIdx.x;
    const int tid = threadIdx.x;

    if (bid < PA_BLOCKS) {
        const int mb = bid & 127, kq = bid >> 7;
        const int mt = tid >> 5, l = tid & 31;
        const int r = l >> 2, c2 = 2 * (l & 3);
        const int m0 = mb * 128 + mt * 16;

        #pragma unroll
        for (int t = 0; t < 4; t++) {
            const int kt = kq * 4 + t;
            const int k0 = kt * 16;
            const float* base = (k0 < DHALF) ? fs : fp;
            const int kk = (k0 < DHALF) ? k0 : k0 - DHALF;

            float2 p0 = *(const float2*)(base + (size_t)(m0 + r)     * DHALF + kk + c2);
            float2 p1 = *(const float2*)(base + (size_t)(m0 + r + 8) * DHALF + kk + c2);
            float2 p2 = *(const float2*)(base + (size_t)(m0 + r)     * DHALF + kk + c2 + 8);
            float2 p3 = *(const float2*)(base + (size_t)(m0 + r + 8) * DHALF + kk + c2 + 8);

            uint4 o;
            o.x = pack_h2(p0.x, p0.y);
            o.y = pack_h2(p1.x, p1.y);
            o.z = pack_h2(p2.x, p2.y);
            o.w = pack_h2(p3.x, p3.y);
            g_At[(((size_t)mb * 128 + kt) * 8 + mt) * 32 + l] = o;
        }
    } else if (bid < PA_BLOCKS + PW1_BLOCKS) {
        const int t = bid - PA_BLOCKS;
        const int kt = t & 127, nb = (t >> 7) & 3, v = t >> 9;
        prep_W_body(gW1, eW1, g_W1t, DIN, H1DIM, kt, nb, v, tid);
    } else {
        const int t = bid - (PA_BLOCKS + PW1_BLOCKS);
        const int kt = t & 31, v = t >> 5;
        prep_W_body(gW2, eW2, g_W2t, H1DIM, H2DIM, kt, 0, v, tid);
    }
}

// ---------------------------------------------------------------------------
// GEMM mainloop (R11 exact: 4 stages, paired B, warp 64x64, 128 threads)
// ---------------------------------------------------------------------------
#define STAGES       4
#define STAGE_BYTES  16384
#define GSTRIDE      8192
#define GEMM_SMEM    (STAGES * STAGE_BYTES)   // 65536

__device__ __forceinline__ void issue_stage(uint32_t sbase, int stage,
                                            const char* gA, const char* gB, int tid)
{
    uint32_t sA = sbase + stage * STAGE_BYTES;
    uint32_t sB = sA + 8192;
    #pragma unroll
    for (int j = 0; j < 4; j++)
        CP16(sA + (uint32_t)(tid + j * 128) * 16, gA + (size_t)(tid + j * 128) * 16);
    #pragma unroll
    for (int j = 0; j < 4; j++)
        CP16(sB + (uint32_t)(tid + j * 128) * 16, gB + (size_t)(tid + j * 128) * 16);
}

__device__ __forceinline__ void compute_stage(const char* smem, int stage,
                                              int wm, int wn, int l,
                                              float acc[4][8][4])
{
    const char* sA = smem + stage * STAGE_BYTES;
    const char* sB = sA + 8192;
    #pragma unroll
    for (int ks = 0; ks < 2; ks++) {
        uint32_t a[4][4], b[8][2];
        #pragma unroll
        for (int i = 0; i < 4; i++) {
            uint4 av = *(const uint4*)(sA + (((ks * 8 + wm * 4 + i) * 32 + l) << 4));
            a[i][0] = av.x; a[i][1] = av.y; a[i][2] = av.z; a[i][3] = av.w;
        }
        #pragma unroll
        for (int p = 0; p < 4; p++) {
            uint4 bv = *(const uint4*)(sB + ks * 4096 + ((wn * 4 + p) * 32 + l) * 16);
            b[2*p][0]   = bv.x; b[2*p][1]   = bv.y;
            b[2*p+1][0] = bv.z; b[2*p+1][1] = bv.w;
        }
        #pragma unroll
        for (int i = 0; i < 4; i++)
            #pragma unroll
            for (int j = 0; j < 8; j++)
                mma16(acc[i][j], a[i], b[j]);
    }
}

template<int NKB>
__device__ __forceinline__ void gemm_mainloop(
    uint32_t sbase, const char* smem, const char* gA0, const char* gB0,
    int tid, int wm, int wn, int l, float acc[4][8][4])
{
    issue_stage(sbase, 0, gA0,               gB0,               tid); CP_COMMIT();
    issue_stage(sbase, 1, gA0 + 1 * GSTRIDE, gB0 + 1 * GSTRIDE, tid); CP_COMMIT();
    issue_stage(sbase, 2, gA0 + 2 * GSTRIDE, gB0 + 2 * GSTRIDE, tid); CP_COMMIT();

    #pragma unroll 4
    for (int kb = 0; kb < NKB; kb++) {
        CP_WAIT2();
        __syncthreads();
        if (kb + 3 < NKB)
            issue_stage(sbase, (kb + 3) & (STAGES - 1),
                        gA0 + (size_t)(kb + 3) * GSTRIDE,
                        gB0 + (size_t)(kb + 3) * GSTRIDE, tid);
        CP_COMMIT();
        compute_stage(smem, kb & (STAGES - 1), wm, wn, l, acc);
    }
    CP_WAIT0();
}

// ---------------------------------------------------------------------------
// gemm1_tc: R11 body, occupancy 3 (12 warps/SM)
// ---------------------------------------------------------------------------
__global__ __launch_bounds__(128, 3) void gemm1_tc(
    const float* __restrict__ gb1, const float* __restrict__ eb1)
{
    extern __shared__ __align__(16) char smem[];
    const uint32_t sbase = smem_u32(smem);
    const int tid = threadIdx.x;
    const int w = tid >> 5, l = tid & 31;
    const int wm = w >> 1, wn = w & 1;
    const int v = blockIdx.x >> 2, nb = blockIdx.x & 3;
    const int mb = blockIdx.y;

    const char* gA0 = (const char*)g_At + (size_t)mb * 128 * 4096;
    const char* gB0 = (const char*)g_W1t + (size_t)(v * 4 + nb) * 128 * 4096;

    float acc[4][8][4];
    #pragma unroll
    for (int i = 0; i < 4; i++)
        #pragma unroll
        for (int j = 0; j < 8; j++)
            #pragma unroll
            for (int q = 0; q < 4; q++) acc[i][j][q] = 0.0f;

    gemm_mainloop<DIN / 32>(sbase, smem, gA0, gB0, tid, wm, wn, l, acc);

    const float* bias = ((v == 0) ? gb1 : (eb1 + (size_t)(v - 1) * H1DIM)) + nb * 128;
    const int c2 = 2 * (l & 3);
    #pragma unroll
    for (int i = 0; i < 4; i++) {
        const int mt = wm * 4 + i;
        #pragma unroll
        for (int jk = 0; jk < 4; jk++) {
            uint4 o;
            {
                const int j = 2 * jk;
                const int cc = wn * 64 + j * 8 + c2;
                const float b0 = __ldg(bias + cc), b1 = __ldg(bias + cc + 1);
                o.x = pack_h2(fmaxf(acc[i][j][0] + b0, 0.0f), fmaxf(acc[i][j][1] + b1, 0.0f));
                o.y = pack_h2(fmaxf(acc[i][j][2] + b0, 0.0f), fmaxf(acc[i][j][3] + b1, 0.0f));
            }
            {
                const int j = 2 * jk + 1;
                const int cc = wn * 64 + j * 8 + c2;
                const float b0 = __ldg(bias + cc), b1 = __ldg(bias + cc + 1);
                o.z = pack_h2(fmaxf(acc[i][j][0] + b0, 0.0f), fmaxf(acc[i][j][1] + b1, 0.0f));
                o.w = pack_h2(fmaxf(acc[i][j][2] + b0, 0.0f), fmaxf(acc[i][j][3] + b1, 0.0f));
            }
            const int kt = nb * 8 + wn * 4 + jk;
            g_H1t[((((size_t)v * 128 + mb) * 32 + kt) * 8 + mt) * 32 + l] = o;
        }
    }
}

// ---------------------------------------------------------------------------
// gemm2_tc: R11 body, occupancy 3
// ---------------------------------------------------------------------------
__global__ __launch_bounds__(128, 3) void gemm2_tc(
    const float* __restrict__ gb2, const float* __restrict__ eb2)
{
    extern __shared__ __align__(16) char smem[];
    const uint32_t sbase = smem_u32(smem);
    const int tid = threadIdx.x;
    const int w = tid >> 5, l = tid & 31;
    const int wm = w >> 1, wn = w & 1;
    const int v = blockIdx.x;
    const int mb = blockIdx.y;

    const char* gA0 = (const char*)g_H1t + (size_t)(v * 128 + mb) * 32 * 4096;
    const char* gB0 = (const char*)g_W2t + (size_t)v * 32 * 4096;

    float acc[4][8][4];
    #pragma unroll
    for (int i = 0; i < 4; i++)
        #pragma unroll
        for (int j = 0; j < 8; j++)
            #pragma unroll
            for (int q = 0; q < 4; q++) acc[i][j][q] = 0.0f;

    gemm_mainloop<H1DIM / 32>(sbase, smem, gA0, gB0, tid, wm, wn, l, acc);

    const float* bias = (v == 0) ? gb2 : (eb2 + (size_t)(v - 1) * H2DIM);
    const int r = l >> 2, c2 = 2 * (l & 3);
    #pragma unroll
    for (int i = 0; i < 4; i++) {
        const int m = mb * 128 + wm * 64 + i * 16 + r;
        float* o0 = g_H2 + ((size_t)v * BATCH + m) * H2DIM;
        float* o1 = g_H2 + ((size_t)v * BATCH + m + 8) * H2DIM;
        #pragma unroll
        for (int j = 0; j < 8; j++) {
            const int n = wn * 64 + j * 8 + c2;
            const float b0 = __ldg(bias + n), b1 = __ldg(bias + n + 1);
            float2 u, d;
            u.x = fmaxf(acc[i][j][0] + b0, 0.0f);
            u.y = fmaxf(acc[i][j][1] + b1, 0.0f);
            d.x = fmaxf(acc[i][j][2] + b0, 0.0f);
            d.y = fmaxf(acc[i][j][3] + b1, 0.0f);
            *(float2*)(o0 + n) = u;
            *(float2*)(o1 + n) = d;
        }
    }
}

// ---------------------------------------------------------------------------
// final_kernel v3 (R11 exact: double-buffered tiles, fp32 W3 tables)
// ---------------------------------------------------------------------------
#define FIN_TILE_STRIDE 132
#define FIN_TILE_BYTES  (128 * FIN_TILE_STRIDE * 4)
#define FIN_WG_OFF      (2 * FIN_TILE_BYTES)
#define FIN_WE_OFF      (FIN_WG_OFF + 128 * 8 * 4)
#define FIN_SP_OFF      (FIN_WE_OFF + 8 * 128 * 12 * 4)
#define FIN_SMEM        (FIN_SP_OFF + 128 * 12 * 4)

__global__ __launch_bounds__(256) void final_kernel(
    const float* __restrict__ gW3, const float* __restrict__ gb3,
    const float* __restrict__ eW3, const float* __restrict__ eb3,
    float* __restrict__ out, int write_gate)
{
    extern __shared__ __align__(16) char smem[];
    const uint32_t sbase = smem_u32(smem);
    const int tid = threadIdx.x;
    const int half = tid >> 7;
    const int tt = tid & 127;
    const int m0 = blockIdx.x * 128;

    float* tile0 = (float*)smem;
    float* tile1 = (float*)(smem + FIN_TILE_BYTES);
    float* wg = (float*)(smem + FIN_WG_OFF);
    float* we = (float*)(smem + FIN_WE_OFF);
    float* sp = (float*)(smem + FIN_SP_OFF);

    for (int i = tid; i < 128 * 8; i += 256) wg[i] = gW3[i];
    for (int i = tid; i < 8 * 128 * NCLS; i += 256) {
        const int e = i / (128 * NCLS);
        const int rem = i - e * 128 * NCLS;
        const int k = rem / NCLS, c = rem - k * NCLS;
        we[(e * 128 + k) * 12 + c] = eW3[i];
    }

    auto issue_tile = [&](uint32_t sdst, int v) {
        const float* src = g_H2 + (size_t)v * BATCH * H2DIM + (size_t)m0 * H2DIM;
        #pragma unroll
        for (int it = 0; it < 16; it++) {
            const int idx = tid + it * 256;
            const int row = idx >> 5, c4 = idx & 31;
            CP16(sdst + (uint32_t)(row * FIN_TILE_STRIDE + c4 * 4) * 4,
                 src + (size_t)row * H2DIM + c4 * 4);
        }
    };

    const uint32_t st0 = sbase;
    const uint32_t st1 = sbase + FIN_TILE_BYTES;

    issue_tile(st0, 0); CP_COMMIT();

    float gate[NEXP];
    float outc[NCLS];
    #pragma unroll
    for (int c = 0; c < NCLS; c++) outc[c] = 0.0f;

    for (int v = 0; v < NV; v++) {
        if (v + 1 < NV) { issue_tile((v & 1) ? st0 : st1, v + 1); CP_COMMIT(); }
        if (v + 1 < NV) { CP_WAIT1(); } else { CP_WAIT0(); }
        __syncthreads();

        const float* row = ((v & 1) ? tile1 : tile0)
                         + (size_t)tt * FIN_TILE_STRIDE + half * 64;

        if (v == 0) {
            float gl[NEXP];
            #pragma unroll
            for (int j = 0; j < NEXP; j++) gl[j] = 0.0f;
            const float* wgh = wg + half * 64 * 8;
            #pragma unroll 4
            for (int k4 = 0; k4 < 16; k4++) {
                const float4 h4 = *(const float4*)(row + k4 * 4);
                const float hv[4] = { h4.x, h4.y, h4.z, h4.w };
                #pragma unroll
                for (int q = 0; q < 4; q++) {
                    const float h = hv[q];
                    const float4 w0 = *(const float4*)(wgh + (k4 * 4 + q) * 8);
                    const float4 w1 = *(const float4*)(wgh + (k4 * 4 + q) * 8 + 4);
                    gl[0] += h * w0.x; gl[1] += h * w0.y; gl[2] += h * w0.z; gl[3] += h * w0.w;
                    gl[4] += h * w1.x; gl[5] += h * w1.y; gl[6] += h * w1.z; gl[7] += h * w1.w;
                }
            }
            if (half == 1) {
                #pragma unroll
                for (int j = 0; j < NEXP; j++) sp[tt * 12 + j] = gl[j];
            }
            __syncthreads();
            if (half == 0) {
                #pragma unroll
                for (int j = 0; j < NEXP; j++)
                    gl[j] += sp[tt * 12 + j] + __ldg(gb3 + j);
                float mx = gl[0];
                #pragma unroll
                for (int j = 1; j < NEXP; j++) mx = fmaxf(mx, gl[j]);
                float s = 0.0f;
                #pragma unroll
                for (int j = 0; j < NEXP; j++) { gate[j] = expf(gl[j] - mx); s += gate[j]; }
                const float inv = 1.0f / s;
                #pragma unroll
                for (int j = 0; j < NEXP; j++) gate[j] *= inv;
            }
        } else {
            const int e = v - 1;
            const float* w = we + ((size_t)e * 128 + half * 64) * 12;
            float le[NCLS];
            #pragma unroll
            for (int c = 0; c < NCLS; c++) le[c] = 0.0f;
            #pragma unroll 4
            for (int k4 = 0; k4 < 16; k4++) {
                const float4 h4 = *(const float4*)(row + k4 * 4);
                const float hv[4] = { h4.x, h4.y, h4.z, h4.w };
                #pragma unroll
                for (int q = 0; q < 4; q++) {
                    const float h = hv[q];
                    const float* wk = w + (k4 * 4 + q) * 12;
                    const float4 w0 = *(const float4*)(wk);
                    const float4 w1 = *(const float4*)(wk + 4);
                    const float2 w2 = *(const float2*)(wk + 8);
                    le[0] += h * w0.x; le[1] += h * w0.y; le[2] += h * w0.z; le[3] += h * w0.w;
                    le[4] += h * w1.x; le[5] += h * w1.y; le[6] += h * w1.z; le[7] += h * w1.w;
                    le[8] += h * w2.x; le[9] += h * w2.y;
                }
            }
            if (half == 1) {
                #pragma unroll
                for (int c = 0; c < NCLS; c++) sp[tt * 12 + c] = le[c];
            }
            __syncthreads();
            if (half == 0) {
                #pragma unroll
                for (int c = 0; c < NCLS; c++)
                    le[c] += sp[tt * 12 + c] + __ldg(eb3 + e * NCLS + c);
                float mxe = le[0];
                #pragma unroll
                for (int c = 1; c < NCLS; c++) mxe = fmaxf(mxe, le[c]);
                float se = 0.0f;
                #pragma unroll
                for (int c = 0; c < NCLS; c++) se += expf(le[c] - mxe);
                const float lse = mxe + logf(se);
                const float ge = gate[e];
                #pragma unroll
                for (int c = 0; c < NCLS; c++) outc[c] += ge * (le[c] - lse);
            }
        }
        __syncthreads();
    }

    if (half == 0) {
        const int m = m0 + tt;
        #pragma unroll
        for (int c = 0; c < NCLS; c++) out[(size_t)m * NCLS + c] = outc[c];
        if (write_gate) {
            float* gate_out = out + (size_t)BATCH * NCLS;
            #pragma unroll
            for (int j = 0; j < NEXP; j++) gate_out[(size_t)m * NEXP + j] = gate[j];
        }
    }
}

// ---------------------------------------------------------------------------
// Launch
// ---------------------------------------------------------------------------
extern "C" void kernel_launch(void* const* d_in, const int* in_sizes, int n_in,
                              void* d_out, int out_size)
{
    const float* fs  = (const float*)d_in[0];
    const float* fp  = (const float*)d_in[1];
    const float* gW1 = (const float*)d_in[2];
    const float* gb1 = (const float*)d_in[3];
    const float* gW2 = (const float*)d_in[4];
    const float* gb2 = (const float*)d_in[5];
    const float* gW3 = (const float*)d_in[6];
    const float* gb3 = (const float*)d_in[7];
    const float* eW1 = (const float*)d_in[8];
    const float* eb1 = (const float*)d_in[9];
    const float* eW2 = (const float*)d_in[10];
    const float* eb2 = (const float*)d_in[11];
    const float* eW3 = (const float*)d_in[12];
    const float* eb3 = (const float*)d_in[13];
    float* out = (float*)d_out;

    const int write_gate = (out_size >= BATCH * (NCLS + NEXP)) ? 1 : 0;

    static int attr_done = 0;
    if (!attr_done) {
        cudaFuncSetAttribute(gemm1_tc, cudaFuncAttributeMaxDynamicSharedMemorySize, GEMM_SMEM);
        cudaFuncSetAttribute(gemm2_tc, cudaFuncAttributeMaxDynamicSharedMemorySize, GEMM_SMEM);
        cudaFuncSetAttribute(final_kernel, cudaFuncAttributeMaxDynamicSharedMemorySize, FIN_SMEM);
        attr_done = 1;
    }

    // Prep (single merged launch)
    prep_all<<<PREP_BLOCKS, 256>>>(fs, fp, gW1, eW1, gW2, eW2);

    // Layer 1 (fp16 tensor, 64x64 warp tile, paired-B, 4 stages, 3 CTAs/SM)
    gemm1_tc<<<dim3(NV * 4, BATCH / 128), 128, GEMM_SMEM>>>(gb1, eb1);
    // Layer 2
    gemm2_tc<<<dim3(NV, BATCH / 128), 128, GEMM_SMEM>>>(gb2, eb2);
    // Layer 3 + softmax/log_softmax + weighted sum (R11 v3)
    final_kernel<<<BATCH / 128, 256, FIN_SMEM>>>(gW3, gb3, eW3, eb3, out, write_gate);
}

// round 16
// speedup vs baseline: 1.1187x; 1.1187x over previous
#include <cuda_runtime.h>
#include <cuda_fp16.h>
#include <cstdint>
#include <cstddef>

#define BATCH   16384
#define DIN     2048
#define DHALF   1024
#define H1DIM   512
#define H2DIM   128
#define NEXP    8
#define NCLS    10
#define NV      9

// ---------------------------------------------------------------------------
// Scratch (__device__ globals) — R11 layouts
// ---------------------------------------------------------------------------
__device__ uint4 g_At [(size_t)128 * 128 * 8 * 32];
__device__ uint4 g_W1t[(size_t)36 * 128 * 8 * 32];
__device__ uint4 g_W2t[(size_t)9 * 32 * 8 * 32];
__device__ uint4 g_H1t[(size_t)9 * 128 * 32 * 8 * 32];
__device__ float g_H2 [(size_t)NV * BATCH * H2DIM];

// ---------------------------------------------------------------------------
// helpers
// ---------------------------------------------------------------------------
__device__ __forceinline__ uint32_t smem_u32(const void* p) {
    uint32_t a;
    asm("{ .reg .u64 t; cvta.to.shared.u64 t, %1; cvt.u32.u64 %0, t; }" : "=r"(a) : "l"(p));
    return a;
}

__device__ __forceinline__ uint32_t pack_h2(float x, float y) {
    __half2 h = __floats2half2_rn(x, y);
    return *(uint32_t*)&h;
}

#define CP16(ds, gs) \
    asm volatile("cp.async.cg.shared.global [%0], [%1], 16;" :: "r"(ds), "l"(gs))
#define CP_COMMIT()  asm volatile("cp.async.commit_group;" ::: "memory")
#define CP_WAIT2()   asm volatile("cp.async.wait_group 2;" ::: "memory")
#define CP_WAIT1()   asm volatile("cp.async.wait_group 1;" ::: "memory")
#define CP_WAIT0()   asm volatile("cp.async.wait_group 0;" ::: "memory")

// m16n8k16 fp16 MMA, fp32 accum, D += A*B (row.col)
__device__ __forceinline__ void mma16(float* d, const uint32_t* a, const uint32_t* b) {
    asm volatile(
        "mma.sync.aligned.m16n8k16.row.col.f32.f16.f16.f32 "
        "{%0,%1,%2,%3}, {%4,%5,%6,%7}, {%8,%9}, {%0,%1,%2,%3};"
        : "+f"(d[0]), "+f"(d[1]), "+f"(d[2]), "+f"(d[3])
        : "r"(a[0]), "r"(a[1]), "r"(a[2]), "r"(a[3]), "r"(b[0]), "r"(b[1]));
}

// ---------------------------------------------------------------------------
// Merged prep (R11 exact)
// ---------------------------------------------------------------------------
#define PA_BLOCKS   4096
#define PW1_BLOCKS  4608
#define PW2_BLOCKS  288
#define PREP_BLOCKS (PA_BLOCKS + PW1_BLOCKS + PW2_BLOCKS)

__device__ __forceinline__ void prep_W_body(
    const float* __restrict__ gw, const float* __restrict__ ew,
    uint4* dst, int K, int N, int kt, int nb, int v, int tid)
{
    const float* W = (v == 0) ? gw : (ew + (size_t)(v - 1) * K * N);
    const int KT = K / 16, NB = N / 128;
    const int k0 = kt * 16;

    if (tid < 256) {
        const int ntp = tid >> 5, l = tid & 31;
        const int c2 = 2 * (l & 3), g = l >> 2;
        const int n0 = nb * 128 + ntp * 16 + g;
        const int n1 = n0 + 8;
        uint4 o;
        o.x = pack_h2(W[(size_t)(k0 + c2)     * N + n0], W[(size_t)(k0 + c2 + 1) * N + n0]);
        o.y = pack_h2(W[(size_t)(k0 + c2 + 8) * N + n0], W[(size_t)(k0 + c2 + 9) * N + n0]);
        o.z = pack_h2(W[(size_t)(k0 + c2)     * N + n1], W[(size_t)(k0 + c2 + 1) * N + n1]);
        o.w = pack_h2(W[(size_t)(k0 + c2 + 8) * N + n1], W[(size_t)(k0 + c2 + 9) * N + n1]);
        dst[((((size_t)v * NB + nb) * KT + kt) * 8 + ntp) * 32 + l] = o;
    }
}

__global__ __launch_bounds__(256) void prep_all(
    const float* __restrict__ fs, const float* __restrict__ fp,
    const float* __restrict__ gW1, const float* __restrict__ eW1,
    const float* __restrict__ gW2, const float* __restrict__ eW2)
{
    const int bid = blockIdx.x;
    const int tid = threadIdx.x;

    if (bid < PA_BLOCKS) {
        const int mb = bid & 127, kq = bid >> 7;
        const int mt = tid >> 5, l = tid & 31;
        const int r = l >> 2, c2 = 2 * (l & 3);
        const int m0 = mb * 128 + mt * 16;

        #pragma unroll
        for (int t = 0; t < 4; t++) {
            const int kt = kq * 4 + t;
            const int k0 = kt * 16;
            const float* base = (k0 < DHALF) ? fs : fp;
            const int kk = (k0 < DHALF) ? k0 : k0 - DHALF;

            float2 p0 = *(const float2*)(base + (size_t)(m0 + r)     * DHALF + kk + c2);
            float2 p1 = *(const float2*)(base + (size_t)(m0 + r + 8) * DHALF + kk + c2);
            float2 p2 = *(const float2*)(base + (size_t)(m0 + r)     * DHALF + kk + c2 + 8);
            float2 p3 = *(const float2*)(base + (size_t)(m0 + r + 8) * DHALF + kk + c2 + 8);

            uint4 o;
            o.x = pack_h2(p0.x, p0.y);
            o.y = pack_h2(p1.x, p1.y);
            o.z = pack_h2(p2.x, p2.y);
            o.w = pack_h2(p3.x, p3.y);
            g_At[(((size_t)mb * 128 + kt) * 8 + mt) * 32 + l] = o;
        }
    } else if (bid < PA_BLOCKS + PW1_BLOCKS) {
        const int t = bid - PA_BLOCKS;
        const int kt = t & 127, nb = (t >> 7) & 3, v = t >> 9;
        prep_W_body(gW1, eW1, g_W1t, DIN, H1DIM, kt, nb, v, tid);
    } else {
        const int t = bid - (PA_BLOCKS + PW1_BLOCKS);
        const int kt = t & 31, v = t >> 5;
        prep_W_body(gW2, eW2, g_W2t, H1DIM, H2DIM, kt, 0, v, tid);
    }
}

// ---------------------------------------------------------------------------
// GEMM mainloop (R11 exact: 4 stages, paired B, warp 64x64, 128 threads)
// ---------------------------------------------------------------------------
#define STAGES       4
#define STAGE_BYTES  16384
#define GSTRIDE      8192
#define GEMM_SMEM    (STAGES * STAGE_BYTES)   // 65536

__device__ __forceinline__ void issue_stage(uint32_t sbase, int stage,
                                            const char* gA, const char* gB, int tid)
{
    uint32_t sA = sbase + stage * STAGE_BYTES;
    uint32_t sB = sA + 8192;
    #pragma unroll
    for (int j = 0; j < 4; j++)
        CP16(sA + (uint32_t)(tid + j * 128) * 16, gA + (size_t)(tid + j * 128) * 16);
    #pragma unroll
    for (int j = 0; j < 4; j++)
        CP16(sB + (uint32_t)(tid + j * 128) * 16, gB + (size_t)(tid + j * 128) * 16);
}

__device__ __forceinline__ void compute_stage(const char* smem, int stage,
                                              int wm, int wn, int l,
                                              float acc[4][8][4])
{
    const char* sA = smem + stage * STAGE_BYTES;
    const char* sB = sA + 8192;
    #pragma unroll
    for (int ks = 0; ks < 2; ks++) {
        uint32_t a[4][4], b[8][2];
        #pragma unroll
        for (int i = 0; i < 4; i++) {
            uint4 av = *(const uint4*)(sA + (((ks * 8 + wm * 4 + i) * 32 + l) << 4));
            a[i][0] = av.x; a[i][1] = av.y; a[i][2] = av.z; a[i][3] = av.w;
        }
        #pragma unroll
        for (int p = 0; p < 4; p++) {
            uint4 bv = *(const uint4*)(sB + ks * 4096 + ((wn * 4 + p) * 32 + l) * 16);
            b[2*p][0]   = bv.x; b[2*p][1]   = bv.y;
            b[2*p+1][0] = bv.z; b[2*p+1][1] = bv.w;
        }
        #pragma unroll
        for (int i = 0; i < 4; i++)
            #pragma unroll
            for (int j = 0; j < 8; j++)
                mma16(acc[i][j], a[i], b[j]);
    }
}

template<int NKB>
__device__ __forceinline__ void gemm_mainloop(
    uint32_t sbase, const char* smem, const char* gA0, const char* gB0,
    int tid, int wm, int wn, int l, float acc[4][8][4])
{
    issue_stage(sbase, 0, gA0,               gB0,               tid); CP_COMMIT();
    issue_stage(sbase, 1, gA0 + 1 * GSTRIDE, gB0 + 1 * GSTRIDE, tid); CP_COMMIT();
    issue_stage(sbase, 2, gA0 + 2 * GSTRIDE, gB0 + 2 * GSTRIDE, tid); CP_COMMIT();

    #pragma unroll 4
    for (int kb = 0; kb < NKB; kb++) {
        CP_WAIT2();
        __syncthreads();
        if (kb + 3 < NKB)
            issue_stage(sbase, (kb + 3) & (STAGES - 1),
                        gA0 + (size_t)(kb + 3) * GSTRIDE,
                        gB0 + (size_t)(kb + 3) * GSTRIDE, tid);
        CP_COMMIT();
        compute_stage(smem, kb & (STAGES - 1), wm, wn, l, acc);
    }
    CP_WAIT0();
}

// ---------------------------------------------------------------------------
// gemm1_tc (R11 exact: occupancy 2)
// ---------------------------------------------------------------------------
__global__ __launch_bounds__(128, 2) void gemm1_tc(
    const float* __restrict__ gb1, const float* __restrict__ eb1)
{
    extern __shared__ __align__(16) char smem[];
    const uint32_t sbase = smem_u32(smem);
    const int tid = threadIdx.x;
    const int w = tid >> 5, l = tid & 31;
    const int wm = w >> 1, wn = w & 1;
    const int v = blockIdx.x >> 2, nb = blockIdx.x & 3;
    const int mb = blockIdx.y;

    const char* gA0 = (const char*)g_At + (size_t)mb * 128 * 4096;
    const char* gB0 = (const char*)g_W1t + (size_t)(v * 4 + nb) * 128 * 4096;

    float acc[4][8][4];
    #pragma unroll
    for (int i = 0; i < 4; i++)
        #pragma unroll
        for (int j = 0; j < 8; j++)
            #pragma unroll
            for (int q = 0; q < 4; q++) acc[i][j][q] = 0.0f;

    gemm_mainloop<DIN / 32>(sbase, smem, gA0, gB0, tid, wm, wn, l, acc);

    const float* bias = ((v == 0) ? gb1 : (eb1 + (size_t)(v - 1) * H1DIM)) + nb * 128;
    const int c2 = 2 * (l & 3);
    #pragma unroll
    for (int i = 0; i < 4; i++) {
        const int mt = wm * 4 + i;
        #pragma unroll
        for (int jk = 0; jk < 4; jk++) {
            uint4 o;
            {
                const int j = 2 * jk;
                const int cc = wn * 64 + j * 8 + c2;
                const float b0 = __ldg(bias + cc), b1 = __ldg(bias + cc + 1);
                o.x = pack_h2(fmaxf(acc[i][j][0] + b0, 0.0f), fmaxf(acc[i][j][1] + b1, 0.0f));
                o.y = pack_h2(fmaxf(acc[i][j][2] + b0, 0.0f), fmaxf(acc[i][j][3] + b1, 0.0f));
            }
            {
                const int j = 2 * jk + 1;
                const int cc = wn * 64 + j * 8 + c2;
                const float b0 = __ldg(bias + cc), b1 = __ldg(bias + cc + 1);
                o.z = pack_h2(fmaxf(acc[i][j][0] + b0, 0.0f), fmaxf(acc[i][j][1] + b1, 0.0f));
                o.w = pack_h2(fmaxf(acc[i][j][2] + b0, 0.0f), fmaxf(acc[i][j][3] + b1, 0.0f));
            }
            const int kt = nb * 8 + wn * 4 + jk;
            g_H1t[((((size_t)v * 128 + mb) * 32 + kt) * 8 + mt) * 32 + l] = o;
        }
    }
}

// ---------------------------------------------------------------------------
// gemm2_tc (R11 exact: occupancy 2)
// ---------------------------------------------------------------------------
__global__ __launch_bounds__(128, 2) void gemm2_tc(
    const float* __restrict__ gb2, const float* __restrict__ eb2)
{
    extern __shared__ __align__(16) char smem[];
    const uint32_t sbase = smem_u32(smem);
    const int tid = threadIdx.x;
    const int w = tid >> 5, l = tid & 31;
    const int wm = w >> 1, wn = w & 1;
    const int v = blockIdx.x;
    const int mb = blockIdx.y;

    const char* gA0 = (const char*)g_H1t + (size_t)(v * 128 + mb) * 32 * 4096;
    const char* gB0 = (const char*)g_W2t + (size_t)v * 32 * 4096;

    float acc[4][8][4];
    #pragma unroll
    for (int i = 0; i < 4; i++)
        #pragma unroll
        for (int j = 0; j < 8; j++)
            #pragma unroll
            for (int q = 0; q < 4; q++) acc[i][j][q] = 0.0f;

    gemm_mainloop<H1DIM / 32>(sbase, smem, gA0, gB0, tid, wm, wn, l, acc);

    const float* bias = (v == 0) ? gb2 : (eb2 + (size_t)(v - 1) * H2DIM);
    const int r = l >> 2, c2 = 2 * (l & 3);
    #pragma unroll
    for (int i = 0; i < 4; i++) {
        const int m = mb * 128 + wm * 64 + i * 16 + r;
        float* o0 = g_H2 + ((size_t)v * BATCH + m) * H2DIM;
        float* o1 = g_H2 + ((size_t)v * BATCH + m + 8) * H2DIM;
        #pragma unroll
        for (int j = 0; j < 8; j++) {
            const int n = wn * 64 + j * 8 + c2;
            const float b0 = __ldg(bias + n), b1 = __ldg(bias + n + 1);
            float2 u, d;
            u.x = fmaxf(acc[i][j][0] + b0, 0.0f);
            u.y = fmaxf(acc[i][j][1] + b1, 0.0f);
            d.x = fmaxf(acc[i][j][2] + b0, 0.0f);
            d.y = fmaxf(acc[i][j][3] + b1, 0.0f);
            *(float2*)(o0 + n) = u;
            *(float2*)(o1 + n) = d;
        }
    }
}

// ---------------------------------------------------------------------------
// final_kernel v3 (R11 structure; inner k-loops fully unrolled, biases hoisted)
// ---------------------------------------------------------------------------
#define FIN_TILE_STRIDE 132
#define FIN_TILE_BYTES  (128 * FIN_TILE_STRIDE * 4)
#define FIN_WG_OFF      (2 * FIN_TILE_BYTES)
#define FIN_WE_OFF      (FIN_WG_OFF + 128 * 8 * 4)
#define FIN_SP_OFF      (FIN_WE_OFF + 8 * 128 * 12 * 4)
#define FIN_SMEM        (FIN_SP_OFF + 128 * 12 * 4)

__global__ __launch_bounds__(256) void final_kernel(
    const float* __restrict__ gW3, const float* __restrict__ gb3,
    const float* __restrict__ eW3, const float* __restrict__ eb3,
    float* __restrict__ out, int write_gate)
{
    extern __shared__ __align__(16) char smem[];
    const uint32_t sbase = smem_u32(smem);
    const int tid = threadIdx.x;
    const int half = tid >> 7;
    const int tt = tid & 127;
    const int m0 = blockIdx.x * 128;

    float* tile0 = (float*)smem;
    float* tile1 = (float*)(smem + FIN_TILE_BYTES);
    float* wg = (float*)(smem + FIN_WG_OFF);
    float* we = (float*)(smem + FIN_WE_OFF);
    float* sp = (float*)(smem + FIN_SP_OFF);

    for (int i = tid; i < 128 * 8; i += 256) wg[i] = gW3[i];
    for (int i = tid; i < 8 * 128 * NCLS; i += 256) {
        const int e = i / (128 * NCLS);
        const int rem = i - e * 128 * NCLS;
        const int k = rem / NCLS, c = rem - k * NCLS;
        we[(e * 128 + k) * 12 + c] = eW3[i];
    }

    auto issue_tile = [&](uint32_t sdst, int v) {
        const float* src = g_H2 + (size_t)v * BATCH * H2DIM + (size_t)m0 * H2DIM;
        #pragma unroll
        for (int it = 0; it < 16; it++) {
            const int idx = tid + it * 256;
            const int row = idx >> 5, c4 = idx & 31;
            CP16(sdst + (uint32_t)(row * FIN_TILE_STRIDE + c4 * 4) * 4,
                 src + (size_t)row * H2DIM + c4 * 4);
        }
    };

    const uint32_t st0 = sbase;
    const uint32_t st1 = sbase + FIN_TILE_BYTES;

    issue_tile(st0, 0); CP_COMMIT();

    // hoist biases out of the per-v path
    float gb3r[NEXP];
    #pragma unroll
    for (int j = 0; j < NEXP; j++) gb3r[j] = __ldg(gb3 + j);

    float gate[NEXP];
    float outc[NCLS];
    #pragma unroll
    for (int c = 0; c < NCLS; c++) outc[c] = 0.0f;

    for (int v = 0; v < NV; v++) {
        if (v + 1 < NV) { issue_tile((v & 1) ? st0 : st1, v + 1); CP_COMMIT(); }
        if (v + 1 < NV) { CP_WAIT1(); } else { CP_WAIT0(); }
        __syncthreads();

        const float* row = ((v & 1) ? tile1 : tile0)
                         + (size_t)tt * FIN_TILE_STRIDE + half * 64;

        if (v == 0) {
            float gl[NEXP];
            #pragma unroll
            for (int j = 0; j < NEXP; j++) gl[j] = 0.0f;
            const float* wgh = wg + half * 64 * 8;
            #pragma unroll
            for (int k4 = 0; k4 < 16; k4++) {
                const float4 h4 = *(const float4*)(row + k4 * 4);
                const float hv[4] = { h4.x, h4.y, h4.z, h4.w };
                #pragma unroll
                for (int q = 0; q < 4; q++) {
                    const float h = hv[q];
                    const float4 w0 = *(const float4*)(wgh + (k4 * 4 + q) * 8);
                    const float4 w1 = *(const float4*)(wgh + (k4 * 4 + q) * 8 + 4);
                    gl[0] += h * w0.x; gl[1] += h * w0.y; gl[2] += h * w0.z; gl[3] += h * w0.w;
                    gl[4] += h * w1.x; gl[5] += h * w1.y; gl[6] += h * w1.z; gl[7] += h * w1.w;
                }
            }
            if (half == 1) {
                #pragma unroll
                for (int j = 0; j < NEXP; j++) sp[tt * 12 + j] = gl[j];
            }
            __syncthreads();
            if (half == 0) {
                #pragma unroll
                for (int j = 0; j < NEXP; j++)
                    gl[j] += sp[tt * 12 + j] + gb3r[j];
                float mx = gl[0];
                #pragma unroll
                for (int j = 1; j < NEXP; j++) mx = fmaxf(mx, gl[j]);
                float s = 0.0f;
                #pragma unroll
                for (int j = 0; j < NEXP; j++) { gate[j] = expf(gl[j] - mx); s += gate[j]; }
                const float inv = 1.0f / s;
                #pragma unroll
                for (int j = 0; j < NEXP; j++) gate[j] *= inv;
            }
        } else {
            const int e = v - 1;
            const float* w = we + ((size_t)e * 128 + half * 64) * 12;
            float le[NCLS];
            #pragma unroll
            for (int c = 0; c < NCLS; c++) le[c] = 0.0f;
            #pragma unroll
            for (int k4 = 0; k4 < 16; k4++) {
                const float4 h4 = *(const float4*)(row + k4 * 4);
                const float hv[4] = { h4.x, h4.y, h4.z, h4.w };
                #pragma unroll
                for (int q = 0; q < 4; q++) {
                    const float h = hv[q];
                    const float* wk = w + (k4 * 4 + q) * 12;
                    const float4 w0 = *(const float4*)(wk);
                    const float4 w1 = *(const float4*)(wk + 4);
                    const float2 w2 = *(const float2*)(wk + 8);
                    le[0] += h * w0.x; le[1] += h * w0.y; le[2] += h * w0.z; le[3] += h * w0.w;
                    le[4] += h * w1.x; le[5] += h * w1.y; le[6] += h * w1.z; le[7] += h * w1.w;
                    le[8] += h * w2.x; le[9] += h * w2.y;
                }
            }
            if (half == 1) {
                #pragma unroll
                for (int c = 0; c < NCLS; c++) sp[tt * 12 + c] = le[c];
            }
            __syncthreads();
            if (half == 0) {
                #pragma unroll
                for (int c = 0; c < NCLS; c++)
                    le[c] += sp[tt * 12 + c] + __ldg(eb3 + e * NCLS + c);
                float mxe = le[0];
                #pragma unroll
                for (int c = 1; c < NCLS; c++) mxe = fmaxf(mxe, le[c]);
                float se = 0.0f;
                #pragma unroll
                for (int c = 0; c < NCLS; c++) se += expf(le[c] - mxe);
                const float lse = mxe + logf(se);
                const float ge = gate[e];
                #pragma unroll
                for (int c = 0; c < NCLS; c++) outc[c] += ge * (le[c] - lse);
            }
        }
        __syncthreads();
    }

    if (half == 0) {
        const int m = m0 + tt;
        #pragma unroll
        for (int c = 0; c < NCLS; c++) out[(size_t)m * NCLS + c] = outc[c];
        if (write_gate) {
            float* gate_out = out + (size_t)BATCH * NCLS;
            #pragma unroll
            for (int j = 0; j < NEXP; j++) gate_out[(size_t)m * NEXP + j] = gate[j];
        }
    }
}

// ---------------------------------------------------------------------------
// Launch
// ---------------------------------------------------------------------------
extern "C" void kernel_launch(void* const* d_in, const int* in_sizes, int n_in,
                              void* d_out, int out_size)
{
    const float* fs  = (const float*)d_in[0];
    const float* fp  = (const float*)d_in[1];
    const float* gW1 = (const float*)d_in[2];
    const float* gb1 = (const float*)d_in[3];
    const float* gW2 = (const float*)d_in[4];
    const float* gb2 = (const float*)d_in[5];
    const float* gW3 = (const float*)d_in[6];
    const float* gb3 = (const float*)d_in[7];
    const float* eW1 = (const float*)d_in[8];
    const float* eb1 = (const float*)d_in[9];
    const float* eW2 = (const float*)d_in[10];
    const float* eb2 = (const float*)d_in[11];
    const float* eW3 = (const float*)d_in[12];
    const float* eb3 = (const float*)d_in[13];
    float* out = (float*)d_out;

    const int write_gate = (out_size >= BATCH * (NCLS + NEXP)) ? 1 : 0;

    static int attr_done = 0;
    if (!attr_done) {
        cudaFuncSetAttribute(gemm1_tc, cudaFuncAttributeMaxDynamicSharedMemorySize, GEMM_SMEM);
        cudaFuncSetAttribute(gemm2_tc, cudaFuncAttributeMaxDynamicSharedMemorySize, GEMM_SMEM);
        cudaFuncSetAttribute(final_kernel, cudaFuncAttributeMaxDynamicSharedMemorySize, FIN_SMEM);
        attr_done = 1;
    }

    // Prep (single merged launch)
    prep_all<<<PREP_BLOCKS, 256>>>(fs, fp, gW1, eW1, gW2, eW2);

    // Layer 1 (fp16 tensor, 64x64 warp tile, paired-B, 4 stages, 2 CTAs/SM)
    gemm1_tc<<<dim3(NV * 4, BATCH / 128), 128, GEMM_SMEM>>>(gb1, eb1);
    // Layer 2
    gemm2_tc<<<dim3(NV, BATCH / 128), 128, GEMM_SMEM>>>(gb2, eb2);
    // Layer 3 + softmax/log_softmax + weighted sum
    final_kernel<<<BATCH / 128, 256, FIN_SMEM>>>(gW3, gb3, eW3, eb3, out, write_gate);
}